// round 2
// baseline (speedup 1.0000x reference)
#include <cuda_runtime.h>

// 16k -> 24k polyphase resampler (torchaudio/kaldi defaults).
// in_unit=2, out_unit=3 phases, first_indices={-6,-5,-4}, W=13 taps.
// out[c, n] = sum_j x[c, (n%3 - 6) + 2*(n/3) + j] * w[n%3][j], zero-padded x.
//
// Tile: T=8 input units -> 24 outputs per thread. Input window:
// global [16t-6, 16t+22] -> load [16t-8, 16t+24) = 32 floats = 8x LDG.128.

#define C_CH    8
#define NPHASE  3
#define WTAPS   13
#define OUT_PT  24   // outputs per thread (8 units x 3 phases)

__global__ __launch_bounds__(128, 5) void resample_16_24_kernel(
    const float* __restrict__ x, const float* __restrict__ wgt,
    float* __restrict__ out, int L, int tot)
{
    const int c = blockIdx.y;
    const long long t  = (long long)blockIdx.x * blockDim.x + threadIdx.x;
    const long long n0 = t * OUT_PT;
    if (n0 >= tot) return;

    const float* xc = x + (size_t)c * (size_t)L;

    // Input window: [g0, g0+32), g0 = 16t - 8 (16B aligned)
    const long long g0 = 16 * t - 8;
    float xin[32];
    if (g0 >= 0 && g0 + 32 <= (long long)L) {
        const float4* p = reinterpret_cast<const float4*>(xc + g0);
#pragma unroll
        for (int q = 0; q < 8; q++) {
            float4 v = __ldg(&p[q]);
            xin[4*q+0] = v.x; xin[4*q+1] = v.y;
            xin[4*q+2] = v.z; xin[4*q+3] = v.w;
        }
    } else {
        // boundary threads (first/last per channel): guarded scalar loads
#pragma unroll
        for (int q = 0; q < 32; q++) {
            long long g = g0 + q;
            xin[q] = (g >= 0 && g < (long long)L) ? xc[g] : 0.0f;
        }
    }

    // Filter bank in registers (uniform broadcast loads, L1-resident)
    float w[NPHASE][WTAPS];
#pragma unroll
    for (int i = 0; i < NPHASE; i++)
#pragma unroll
        for (int j = 0; j < WTAPS; j++)
            w[i][j] = __ldg(&wgt[i * WTAPS + j]);

    // 24 outputs; output n (relative) has phase i=n%3, unit u=n/3,
    // and reads xin[(2+i+2u) .. +12]. Compute quad-by-quad and store
    // immediately to keep accumulator liveness at 4 regs.
    float* oc = out + (size_t)c * (size_t)tot + n0;
    float4* po = reinterpret_cast<float4*>(oc);

#pragma unroll
    for (int q = 0; q < 6; q++) {
        float o4[4];
#pragma unroll
        for (int r = 0; r < 4; r++) {
            const int n = 4 * q + r;
            const int u = n / 3;
            const int i = n % 3;
            const int base = 2 + i + 2 * u;
            float s = 0.0f;
#pragma unroll
            for (int j = 0; j < WTAPS; j++)
                s = fmaf(xin[base + j], w[i][j], s);
            o4[r] = s;
        }
        po[q] = make_float4(o4[0], o4[1], o4[2], o4[3]);
    }
}

extern "C" void kernel_launch(void* const* d_in, const int* in_sizes, int n_in,
                              void* d_out, int out_size)
{
    const float* x   = (const float*)d_in[0];
    const float* wgt = (const float*)d_in[1];
    float* out = (float*)d_out;

    const int L   = in_sizes[0] / C_CH;   // 4,000,000
    const int tot = out_size   / C_CH;    // 6,000,000 (divisible by 24)

    const long long threads_per_ch = ((long long)tot + OUT_PT - 1) / OUT_PT;
    const int block = 128;
    const int bx = (int)((threads_per_ch + block - 1) / block);
    dim3 grid(bx, C_CH);
    resample_16_24_kernel<<<grid, block>>>(x, wgt, out, L, tot);
}